// round 15
// baseline (speedup 1.0000x reference)
#include <cuda_runtime.h>
#include <math.h>

// ---------------------------------------------------------------------------
// GCN 2-layer forward:  out = log_softmax( A' relu(A' (x W1) + b1) W2 + b2 )
// A' = D^-1/2 (A + I) D^-1/2.
//
// Locked-in session rule: random gathers ONLY from harness buffers (x, d_out);
// __device__ globals used for streaming access only (small-page TLB thrash).
//
//   0 k_hist        degree histogram
//   1 k_scan_fused  rowoff/cursor/dinv, restores g_cnt=0
//   2 k_scatter     CSR fill
//   3 k_agg1        ax = dinv*(dinv*x_i + sum dinv_j x_j)   <- ncu slot (16-wide)
//   4 k_gemm<128,1> h2 = relu(ax W1 + b1)        (K-chunked, 49KB smem)
//   5 k_gemm<64,0>  d_out := zs = dinv * (h2 W2) (K-chunked)
//   6 k_agg2sm      z2 = log_softmax(dinv*(sum zs_j + zs_i) + b2) [gathers d_out]
//   7 k_copy        d_out := z2
// ---------------------------------------------------------------------------

#define NMAX 100000
#define EMAX 1600000

__device__ int g_cnt[NMAX];          // zero at module load; self-restored each call
__device__ int g_rowoff[NMAX + 1];
__device__ int g_cursor[NMAX];
__device__ float g_dinv[NMAX];
__device__ int g_csr[EMAX];
__device__ __align__(16) float g_ax[(size_t)NMAX * 128];   // A'x (streaming only)
__device__ __align__(16) float g_h2[(size_t)NMAX * 128];   // relu(ax W1 + b1)
__device__ __align__(16) float g_z2[(size_t)NMAX * 64];    // final log-softmax rows

// ---------------------------------------------------------------------------
__global__ void k_hist(const int* __restrict__ dst, int e) {
    int i = blockIdx.x * blockDim.x + threadIdx.x;
    if (i < e) atomicAdd(&g_cnt[dst[i]], 1);
}

// Single-block fused: exclusive scan of g_cnt -> g_rowoff & g_cursor,
// dinv = rsqrt(cnt+1), and zero g_cnt (restore invariant for next call).
__global__ void k_scan_fused(int n, int e) {
    __shared__ int warp_sums[32];
    __shared__ int s_base;
    const int t = threadIdx.x;
    const int lane = t & 31, wid = t >> 5;
    if (t == 0) s_base = 0;
    __syncthreads();

    for (int start = 0; start < n; start += 1024) {
        int i = start + t;
        int v = (i < n) ? g_cnt[i] : 0;

        int sc = v;
#pragma unroll
        for (int o = 1; o < 32; o <<= 1) {
            int u = __shfl_up_sync(0xffffffffu, sc, o);
            if (lane >= o) sc += u;
        }
        if (lane == 31) warp_sums[wid] = sc;
        __syncthreads();
        if (wid == 0) {
            int ws = warp_sums[lane];
#pragma unroll
            for (int o = 1; o < 32; o <<= 1) {
                int u = __shfl_up_sync(0xffffffffu, ws, o);
                if (lane >= o) ws += u;
            }
            warp_sums[lane] = ws;
        }
        __syncthreads();

        int excl = sc - v + (wid ? warp_sums[wid - 1] : 0) + s_base;
        if (i < n) {
            g_rowoff[i] = excl;
            g_cursor[i] = excl;
            g_dinv[i] = rsqrtf((float)(v + 1));  // +1 self loop
            g_cnt[i] = 0;
        }
        __syncthreads();
        if (t == 0) s_base += warp_sums[31];
        __syncthreads();
    }
    if (t == 0) g_rowoff[n] = e;
}

__global__ void k_scatter(const int* __restrict__ src, const int* __restrict__ dst, int e) {
    int i = blockIdx.x * blockDim.x + threadIdx.x;
    if (i < e) {
        int d = dst[i];
        int p = atomicAdd(&g_cursor[d], 1);
        g_csr[p] = src[i];
    }
}

// ---------------------------------------------------------------------------
// Layer-1 aggregation on raw input x (aggregate-first). Block = 128 threads
// = one node, thread = column. 16-wide inner batch: a typical node's whole
// neighbor set (avg deg 16) is in flight at once.
//   ax[i,t] = dinv_i * ( dinv_i * x[i,t] + sum_j dinv_j * x[j,t] )
// ---------------------------------------------------------------------------
#define AGG_CH 128

__global__ void k_agg1(const float* __restrict__ x, float* __restrict__ out, int n) {
    __shared__ int s_idx[AGG_CH];
    __shared__ float s_d[AGG_CH];
    const int node = blockIdx.x;
    const int t = threadIdx.x;
    const float* __restrict__ xc = x + t;

    const float di = g_dinv[node];
    float acc = di * xc[(size_t)node * 128];  // self loop

    const int p = g_rowoff[node];
    const int end = g_rowoff[node + 1];

    for (int base = p; base < end; base += AGG_CH) {
        const int nv = min(AGG_CH, end - base);
        __syncthreads();
        if (t < nv) {
            int j = g_csr[base + t];
            s_idx[t] = j;
            s_d[t] = g_dinv[j];
        }
        __syncthreads();
        int m = 0;
        for (; m + 16 <= nv; m += 16) {
            float v[16], d[16];
#pragma unroll
            for (int q = 0; q < 16; q++) {
                int j = s_idx[m + q];
                d[q] = s_d[m + q];
                v[q] = xc[(size_t)j * 128];
            }
#pragma unroll
            for (int q = 0; q < 16; q++) acc = fmaf(d[q], v[q], acc);
        }
        for (; m + 4 <= nv; m += 4) {
            int j0 = s_idx[m + 0], j1 = s_idx[m + 1], j2 = s_idx[m + 2], j3 = s_idx[m + 3];
            float d0 = s_d[m + 0], d1 = s_d[m + 1], d2 = s_d[m + 2], d3 = s_d[m + 3];
            float v0 = xc[(size_t)j0 * 128];
            float v1 = xc[(size_t)j1 * 128];
            float v2 = xc[(size_t)j2 * 128];
            float v3 = xc[(size_t)j3 * 128];
            acc = fmaf(d0, v0, acc); acc = fmaf(d1, v1, acc);
            acc = fmaf(d2, v2, acc); acc = fmaf(d3, v3, acc);
        }
        for (; m < nv; m++)
            acc = fmaf(s_d[m], xc[(size_t)s_idx[m] * 128], acc);
    }

    out[(size_t)node * 128 + t] = di * acc;
}

// ---------------------------------------------------------------------------
// GEMM, K-chunked: acc[i][c] = sum_k X[i][k]*W[k][c]   (K = 128 in 4x32)
// Thread owns 4 rows x TN CONSECUTIVE cols -> W reads LDS.128, stores STG.128.
// smem = Xs(64x129) + Ws(32xNC) = 49KB (NC=128) -> 4 blocks/SM.
// EPI 0: out = dinv[i]*acc ; EPI 1: out = relu(acc + bias[c])
// ---------------------------------------------------------------------------
#define XS_STRIDE 129

template <int NC, int EPI>
__global__ void k_gemm(const float* __restrict__ X, const float* __restrict__ W,
                       const float* __restrict__ bias, float* __restrict__ out, int n) {
    extern __shared__ float sm[];
    float* Xs = sm;                    // 64 * 129
    float* Ws = sm + 64 * XS_STRIDE;   // 32 * NC (K-chunk)
    const int tid = threadIdx.x;
    const int row0 = blockIdx.x * 64;

    for (int i = tid; i < 64 * 128; i += 256) {
        int r = i >> 7, c = i & 127;
        int gr = row0 + r;
        Xs[r * XS_STRIDE + c] = (gr < n) ? X[(size_t)gr * 128 + c] : 0.f;
    }

    const int tr = tid >> 4;           // 0..15 -> rows tr*4..tr*4+3
    const int tc = tid & 15;           // cols tc*TN .. tc*TN+TN-1
    constexpr int TN = NC / 16;        // 8 (NC=128) or 4 (NC=64)
    float acc[4][TN];
#pragma unroll
    for (int r = 0; r < 4; r++)
#pragma unroll
        for (int j = 0; j < TN; j++) acc[r][j] = 0.f;

#pragma unroll
    for (int kc = 0; kc < 4; kc++) {
        __syncthreads();   // Xs ready (iter 0) / previous Ws chunk consumed
        for (int i = tid; i < 8 * NC; i += 256)
            ((float4*)Ws)[i] = ((const float4*)(W + kc * 32 * NC))[i];
        __syncthreads();

#pragma unroll 4
        for (int k = 0; k < 32; k++) {
            float xr[4];
#pragma unroll
            for (int r = 0; r < 4; r++)
                xr[r] = Xs[(tr * 4 + r) * XS_STRIDE + kc * 32 + k];
            float4 w[TN / 4];
#pragma unroll
            for (int j4 = 0; j4 < TN / 4; j4++)
                w[j4] = *(const float4*)&Ws[k * NC + tc * TN + j4 * 4];
#pragma unroll
            for (int r = 0; r < 4; r++)
#pragma unroll
                for (int j4 = 0; j4 < TN / 4; j4++) {
                    acc[r][j4 * 4 + 0] = fmaf(xr[r], w[j4].x, acc[r][j4 * 4 + 0]);
                    acc[r][j4 * 4 + 1] = fmaf(xr[r], w[j4].y, acc[r][j4 * 4 + 1]);
                    acc[r][j4 * 4 + 2] = fmaf(xr[r], w[j4].z, acc[r][j4 * 4 + 2]);
                    acc[r][j4 * 4 + 3] = fmaf(xr[r], w[j4].w, acc[r][j4 * 4 + 3]);
                }
        }
    }

    float4 bv[TN / 4];
    if (EPI == 1) {
#pragma unroll
        for (int j4 = 0; j4 < TN / 4; j4++)
            bv[j4] = *(const float4*)&bias[tc * TN + j4 * 4];
    }

#pragma unroll
    for (int r = 0; r < 4; r++) {
        int gr = row0 + tr * 4 + r;
        if (gr < n) {
            if (EPI == 0) {
                float dv = g_dinv[gr];
#pragma unroll
                for (int j4 = 0; j4 < TN / 4; j4++) {
                    float4 o;
                    o.x = dv * acc[r][j4 * 4 + 0];
                    o.y = dv * acc[r][j4 * 4 + 1];
                    o.z = dv * acc[r][j4 * 4 + 2];
                    o.w = dv * acc[r][j4 * 4 + 3];
                    *(float4*)&out[(size_t)gr * NC + tc * TN + j4 * 4] = o;
                }
            } else {
#pragma unroll
                for (int j4 = 0; j4 < TN / 4; j4++) {
                    float4 o;
                    o.x = fmaxf(acc[r][j4 * 4 + 0] + bv[j4].x, 0.f);
                    o.y = fmaxf(acc[r][j4 * 4 + 1] + bv[j4].y, 0.f);
                    o.z = fmaxf(acc[r][j4 * 4 + 2] + bv[j4].z, 0.f);
                    o.w = fmaxf(acc[r][j4 * 4 + 3] + bv[j4].w, 0.f);
                    *(float4*)&out[(size_t)gr * NC + tc * TN + j4 * 4] = o;
                }
            }
        }
    }
}

// ---------------------------------------------------------------------------
// Layer-2 aggregation + bias + log_softmax. Block = 64 threads = one node.
// Gathers zs rows FROM d_out (harness buffer). Rows prescaled by dinv_j.
// ---------------------------------------------------------------------------
__global__ void k_agg2sm(const float* __restrict__ zs, const float* __restrict__ bias,
                         float* __restrict__ outz, int n) {
    __shared__ int s_idx[64];
    __shared__ float s_m[2], s_s[2];
    const int node = blockIdx.x;
    const int t = threadIdx.x;        // 0..63 column
    const int lane = t & 31, wid = t >> 5;
    const float* __restrict__ zc = zs + t;

    float acc = zc[(size_t)node * 64];   // self loop
    const int p = g_rowoff[node];
    const int end = g_rowoff[node + 1];

    for (int base = p; base < end; base += 64) {
        const int nv = min(64, end - base);
        __syncthreads();
        if (t < nv) s_idx[t] = g_csr[base + t];
        __syncthreads();
        int m = 0;
        for (; m + 16 <= nv; m += 16) {
            float v[16];
#pragma unroll
            for (int q = 0; q < 16; q++) v[q] = zc[(size_t)s_idx[m + q] * 64];
#pragma unroll
            for (int q = 0; q < 16; q++) acc += v[q];
        }
        for (; m + 4 <= nv; m += 4) {
            float v0 = zc[(size_t)s_idx[m + 0] * 64];
            float v1 = zc[(size_t)s_idx[m + 1] * 64];
            float v2 = zc[(size_t)s_idx[m + 2] * 64];
            float v3 = zc[(size_t)s_idx[m + 3] * 64];
            acc += (v0 + v1) + (v2 + v3);
        }
        for (; m < nv; m++)
            acc += zc[(size_t)s_idx[m] * 64];
    }

    float o = fmaf(g_dinv[node], acc, bias[t]);

    // log_softmax over the 64 values held by this block (2 warps)
    float mx = o;
#pragma unroll
    for (int off = 16; off; off >>= 1) mx = fmaxf(mx, __shfl_xor_sync(0xffffffffu, mx, off));
    if (lane == 0) s_m[wid] = mx;
    __syncthreads();
    mx = fmaxf(s_m[0], s_m[1]);

    float ss = expf(o - mx);
#pragma unroll
    for (int off = 16; off; off >>= 1) ss += __shfl_xor_sync(0xffffffffu, ss, off);
    if (lane == 0) s_s[wid] = ss;
    __syncthreads();
    float lse = mx + logf(s_s[0] + s_s[1]);

    outz[(size_t)node * 64 + t] = o - lse;
}

// float4 copy: d_out := g_z2
__global__ void k_copy(float4* __restrict__ dst, const float4* __restrict__ src, int n4) {
    int i = blockIdx.x * blockDim.x + threadIdx.x;
    if (i < n4) dst[i] = src[i];
}

// ---------------------------------------------------------------------------
extern "C" void kernel_launch(void* const* d_in, const int* in_sizes, int n_in,
                              void* d_out, int out_size) {
    const float* x  = (const float*)d_in[0];
    const int*   ei = (const int*)d_in[1];
    const float* W1 = (const float*)d_in[2];
    const float* b1 = (const float*)d_in[3];
    const float* W2 = (const float*)d_in[4];
    const float* b2 = (const float*)d_in[5];
    float* out = (float*)d_out;

    const int n = in_sizes[0] / 128;
    const int e = in_sizes[1] / 2;
    const int* src = ei;
    const int* dst = ei + e;

    const int TB = 256;
    const int gE = (e + TB - 1) / TB;
    const int gG = (n + 63) / 64;
    const int n4 = n * 16;                      // n*64 floats / 4
    const int gC = (n4 + TB - 1) / TB;

    const int SM1 = (64 * XS_STRIDE + 32 * 128) * 4;   // 49408 B -> 4 blocks/SM
    const int SM2 = (64 * XS_STRIDE + 32 * 64) * 4;    // 41216 B
    cudaFuncSetAttribute((const void*)k_gemm<128, 1>, cudaFuncAttributeMaxDynamicSharedMemorySize, SM1);
    cudaFuncSetAttribute((const void*)k_gemm<64, 0>,  cudaFuncAttributeMaxDynamicSharedMemorySize, SM2);

    k_hist<<<gE, TB>>>(dst, e);                                   // 0
    k_scan_fused<<<1, 1024>>>(n, e);                              // 1
    k_scatter<<<gE, TB>>>(src, dst, e);                           // 2
    k_agg1<<<n, 128>>>(x, g_ax, n);                               // 3  <- ncu slot
    k_gemm<128, 1><<<gG, 256, SM1>>>(g_ax, W1, b1, g_h2, n);      // 4
    k_gemm<64, 0><<<gG, 256, SM2>>>(g_h2, W2, nullptr, out, n);   // 5  zs -> d_out
    k_agg2sm<<<n, 64>>>(out, b2, g_z2, n);                        // 6  gathers d_out
    k_copy<<<gC, TB>>>((float4*)out, (const float4*)g_z2, n4);    // 7
}